// round 3
// baseline (speedup 1.0000x reference)
#include <cuda_runtime.h>
#include <math.h>
#include <stdint.h>

#define B 32
#define H 480
#define W 640
#define HW (H*W)
#define NPIX (B*HW)
#define TOPK 1024
#define MAXC 16384

// ---- scratch (device globals; zero-initialized at load, self-restoring) ----
__device__ float g_s1m[NPIX];                      // masked score1 (dense, sparse-read later)
__device__ float g_gt[NPIX];                       // sparse gt map (zero invariant across replays)
__device__ unsigned long long g_cand[2ULL*B*MAXC]; // candidate keys, 2 streams
__device__ unsigned long long g_sel[B*TOPK];       // selected gt keys (for correction)
__device__ int    g_cnt[2*B];
__device__ int    g_selcnt[B];
__device__ int    g_norm32[B];
__device__ double g_lossA[B];                      // sum s1m^2 per batch
__device__ double g_lossC;                         // sparse correction
__device__ float  g_gauss[25];

// ---------------------------------------------------------------- init
__global__ void init_kernel() {
    int i = threadIdx.x;
    if (i < 2*B) g_cnt[i] = 0;
    if (i < B)   { g_selcnt[i] = 0; g_norm32[i] = 0; g_lossA[i] = 0.0; }
    if (i == 0)  g_lossC = 0.0;
    if (i < 25) {
        int r = i / 5, c = i % 5;
        double g[5]; double s = 0.0;
        #pragma unroll
        for (int t = 0; t < 5; t++) { g[t] = exp(-((double)((t-2)*(t-2))) / 8.0); s += g[t]; }
        g_gauss[i] = (float)(g[r] * g[c] / (s * s));
    }
}

// visibility value at output pixel (X,Y): bilinear sample of ones image > 0
__device__ __forceinline__ bool visval(const float* h, float X, float Y) {
    float z  = __fmaf_rn(h[6], X, __fmaf_rn(h[7], Y, h[8])) + 1e-8f;
    float px = __fmaf_rn(h[0], X, __fmaf_rn(h[1], Y, h[2])) / z;
    float py = __fmaf_rn(h[3], X, __fmaf_rn(h[4], Y, h[5])) / z;
    float x0 = floorf(px), y0 = floorf(py);
    float fx = px - x0, fy = py - y0;
    float v00 = (x0      >= 0.f && x0      <= (float)(W-1) && y0      >= 0.f && y0      <= (float)(H-1)) ? 1.f : 0.f;
    float v01 = (x0+1.f  >= 0.f && x0+1.f  <= (float)(W-1) && y0      >= 0.f && y0      <= (float)(H-1)) ? 1.f : 0.f;
    float v10 = (x0      >= 0.f && x0      <= (float)(W-1) && y0+1.f  >= 0.f && y0+1.f  <= (float)(H-1)) ? 1.f : 0.f;
    float v11 = (x0+1.f  >= 0.f && x0+1.f  <= (float)(W-1) && y0+1.f  >= 0.f && y0+1.f  <= (float)(H-1)) ? 1.f : 0.f;
    float m = v00*(1.f-fx)*(1.f-fy) + v01*fx*(1.f-fy) + v10*(1.f-fx)*fy + v11*fx*fy;
    return m > 0.f;
}

__device__ __forceinline__ float bilin(const float* __restrict__ img, const float* h,
                                       float X, float Y) {
    float z  = __fmaf_rn(h[6], X, __fmaf_rn(h[7], Y, h[8])) + 1e-8f;
    float px = __fmaf_rn(h[0], X, __fmaf_rn(h[1], Y, h[2])) / z;
    float py = __fmaf_rn(h[3], X, __fmaf_rn(h[4], Y, h[5])) / z;
    float x0 = floorf(px), y0 = floorf(py);
    float fx = px - x0, fy = py - y0;
    float v00 = 0.f, v01 = 0.f, v10 = 0.f, v11 = 0.f;
    if (x0     >= 0.f && x0     <= (float)(W-1) && y0     >= 0.f && y0     <= (float)(H-1)) v00 = img[(int)y0 * W + (int)x0];
    if (x0+1.f >= 0.f && x0+1.f <= (float)(W-1) && y0     >= 0.f && y0     <= (float)(H-1)) v01 = img[(int)y0 * W + (int)(x0+1.f)];
    if (x0     >= 0.f && x0     <= (float)(W-1) && y0+1.f >= 0.f && y0+1.f <= (float)(H-1)) v10 = img[(int)(y0+1.f) * W + (int)x0];
    if (x0+1.f >= 0.f && x0+1.f <= (float)(W-1) && y0+1.f >= 0.f && y0+1.f <= (float)(H-1)) v11 = img[(int)(y0+1.f) * W + (int)(x0+1.f)];
    return v00*(1.f-fx)*(1.f-fy) + v01*fx*(1.f-fy) + v10*(1.f-fx)*fy + v11*fx*fy;
}

// warp-aggregated candidate append (all 32 lanes must reach this call)
__device__ __forceinline__ void append_cand(int list, bool is_cand, unsigned long long key,
                                            int lane) {
    unsigned m = __ballot_sync(0xffffffffu, is_cand);
    if (m) {
        int leader = __ffs(m) - 1;
        int base = 0;
        if (lane == leader) base = atomicAdd(&g_cnt[list], __popc(m));
        base = __shfl_sync(0xffffffffu, base, leader);
        if (is_cand) {
            int p = base + __popc(m & ((1u << lane) - 1));
            if (p < MAXC) g_cand[(size_t)list * MAXC + p] = key;
        }
    }
}

// ----------------- fused warp + erode + mask + NMS + partial-loss pass ------
__global__ void mega_kernel(const float* __restrict__ score1,
                            const float* __restrict__ score2,
                            const float* __restrict__ homo,
                            float* __restrict__ out_vis) {
    __shared__ float h[9];
    __shared__ unsigned char mk[14][38];   // mask, gy in [by-3, by+10], gx in [bx-3, bx+34]
    __shared__ float t1[12][36];           // s1*vis (halo 2), -inf outside image
    __shared__ float t2[12][36];           // w2*vis (halo 2), -inf outside image
    int b  = blockIdx.z;
    int bx = blockIdx.x * 32, by = blockIdx.y * 8;
    int tx = threadIdx.x, ty = threadIdx.y;
    int tid = ty * 32 + tx, lane = tx;
    if (tid < 9) h[tid] = homo[b*9 + tid];
    __syncthreads();

    // 1) visibility mask tile (zero outside image, matching zero-pad erode)
    for (int j = tid; j < 14*38; j += 256) {
        int my = j / 38, mx = j % 38;
        int gy = by - 3 + my, gx = bx - 3 + mx;
        bool v = false;
        if (gx >= 0 && gx < W && gy >= 0 && gy < H)
            v = visval(h, (float)gx, (float)gy);
        mk[my][mx] = v ? 1 : 0;
    }
    __syncthreads();

    // 2) value tiles with halo 2 (erode mask + sample)
    const float* img2 = score2 + (size_t)b * HW;
    const float* img1 = score1 + (size_t)b * HW;
    for (int j = tid; j < 12*36; j += 256) {
        int r = j / 36, c = j % 36;
        int gy = by - 2 + r, gx = bx - 2 + c;
        float v1 = -INFINITY, v2 = -INFINITY;
        if (gx >= 0 && gx < W && gy >= 0 && gy < H) {
            int e = mk[r][c]   & mk[r][c+1]   & mk[r][c+2]
                  & mk[r+1][c] & mk[r+1][c+1] & mk[r+1][c+2]
                  & mk[r+2][c] & mk[r+2][c+1] & mk[r+2][c+2];
            float vis = e ? 1.f : 0.f;
            v1 = img1[gy*W + gx] * vis;
            v2 = bilin(img2, h, (float)gx, (float)gy) * vis;
        }
        t1[r][c] = v1; t2[r][c] = v2;
    }
    __syncthreads();

    // 3) per-pixel outputs + NMS
    int x = bx + tx, y = by + ty;
    int e = mk[ty+2][tx+2] & mk[ty+2][tx+3] & mk[ty+2][tx+4]
          & mk[ty+3][tx+2] & mk[ty+3][tx+3] & mk[ty+3][tx+4]
          & mk[ty+4][tx+2] & mk[ty+4][tx+3] & mk[ty+4][tx+4];
    float visf = e ? 1.f : 0.f;
    float s1v = t1[ty+2][tx+2];
    float w2v = t2[ty+2][tx+2];

    size_t i = (size_t)b * HW + (size_t)y * W + x;
    out_vis[i] = visf;
    g_s1m[i]   = s1v;

    float mx1 = -INFINITY, mx2 = -INFINITY;
    #pragma unroll
    for (int dy = 0; dy < 5; dy++) {
        #pragma unroll
        for (int dx = 0; dx < 5; dx++) {
            mx1 = fmaxf(mx1, t1[ty+dy][tx+dx]);
            mx2 = fmaxf(mx2, t2[ty+dy][tx+dx]);
        }
    }
    int idx = y*W + x;
    unsigned long long key1 = ((unsigned long long)__float_as_uint(s1v) << 32) | (unsigned)(~idx);
    unsigned long long key2 = ((unsigned long long)__float_as_uint(w2v) << 32) | (unsigned)(~idx);
    append_cand(b,     (s1v > 0.3f) && (s1v == mx1), key1, lane);
    append_cand(B + b, (w2v > 0.3f) && (w2v == mx2), key2, lane);

    // 4) partial loss: sum s1m^2 (warp shuffle reduce -> per-batch atomic)
    double a = (double)s1v * (double)s1v;
    #pragma unroll
    for (int o = 16; o > 0; o >>= 1) a += __shfl_down_sync(0xffffffffu, a, o);
    if (lane == 0) atomicAdd(&g_lossA[b], a);

    // 5) norm count
    int cnt = __syncthreads_count(e);
    if (tid == 0) atomicAdd(&g_norm32[b], cnt);
}

// ------------------------------------ top-1024 select + sort + kp/gt output
__global__ void __launch_bounds__(1024) select_kernel(float* __restrict__ out) {
    extern __shared__ unsigned long long sk[];      // cached candidate keys (MAXC)
    __shared__ unsigned long long sel[TOPK];
    __shared__ unsigned int hist[256];
    __shared__ unsigned long long sh_pref;
    __shared__ unsigned int sh_rem;
    __shared__ int sh_cnt;

    int b = blockIdx.x, s = blockIdx.y;
    int li = s*B + b;
    int n = g_cnt[li]; if (n > MAXC) n = MAXC;
    const unsigned long long* keys = g_cand + (size_t)li * MAXC;
    int tid = threadIdx.x;

    sel[tid] = 0ULL;
    if (tid == 0) { sh_pref = 0ULL; sh_rem = TOPK; sh_cnt = 0; }
    for (int i = tid; i < n; i += 1024) sk[i] = keys[i];
    __syncthreads();

    if (n > TOPK) {
        // radix-select the exact 1024th-largest key (keys unique via idx bits)
        for (int shift = 56; shift >= 0; shift -= 8) {
            if (tid < 256) hist[tid] = 0;
            __syncthreads();
            unsigned long long pref  = sh_pref;
            unsigned long long pmask = (shift == 56) ? 0ULL : (~0ULL << (shift + 8));
            for (int i = tid; i < n; i += 1024) {
                unsigned long long k = sk[i];
                if ((k & pmask) == pref)
                    atomicAdd(&hist[(unsigned)(k >> shift) & 255u], 1u);
            }
            __syncthreads();
            if (tid == 0) {
                unsigned rem = sh_rem;
                for (int bin = 255; bin >= 0; bin--) {
                    unsigned c = hist[bin];
                    if (c < rem) rem -= c;
                    else { sh_pref = pref | ((unsigned long long)bin << shift); break; }
                }
                sh_rem = rem;
            }
            __syncthreads();
        }
        unsigned long long kth = sh_pref;
        for (int i = tid; i < n; i += 1024) {
            unsigned long long k = sk[i];
            if (k >= kth) { int p = atomicAdd(&sh_cnt, 1); if (p < TOPK) sel[p] = k; }
        }
    } else {
        if (tid < n) sel[tid] = sk[tid];
    }
    __syncthreads();

    int m = (n < TOPK) ? n : TOPK;

    if (s == 0) {
        // sort needed only for kp output order: bitonic, descending
        for (unsigned k = 2; k <= TOPK; k <<= 1) {
            for (unsigned j = k >> 1; j > 0; j >>= 1) {
                unsigned i = (unsigned)tid, ixj = i ^ j;
                if (ixj > i) {
                    unsigned long long a = sel[i], c = sel[ixj];
                    bool up = ((i & k) == 0);
                    bool sw = up ? (a < c) : (a > c);
                    if (sw) { sel[i] = c; sel[ixj] = a; }
                }
                __syncthreads();
            }
        }
        if (tid < m) {
            unsigned idx = ~(unsigned)(sel[tid] & 0xFFFFFFFFu);
            out[1 + ((size_t)b*TOPK + tid)*2]     = (float)(idx / W);
            out[1 + ((size_t)b*TOPK + tid)*2 + 1] = (float)(idx % W);
        }
        __syncthreads();
        // jax top_k pad semantics: remaining slots = lowest zero-valued indices
        if (tid == 0 && m < TOPK) {
            int cursor = 0;
            for (int j = m; j < TOPK; j++) {
                for (;;) {
                    bool isc = false;
                    for (int t = 0; t < m; t++) {
                        unsigned idx = ~(unsigned)(sel[t] & 0xFFFFFFFFu);
                        if ((int)idx == cursor) { isc = true; break; }
                    }
                    if (!isc) break;
                    cursor++;
                }
                out[1 + ((size_t)b*TOPK + j)*2]     = (float)(cursor / W);
                out[1 + ((size_t)b*TOPK + j)*2 + 1] = (float)(cursor % W);
                cursor++;
            }
        }
    } else {
        // gt stream: no sort needed; persist selection + scatter gaussians
        if (tid == 0) g_selcnt[b] = m;
        if (tid < m) {
            unsigned long long kk = sel[tid];
            g_sel[(size_t)b*TOPK + tid] = kk;
            float v = __uint_as_float((unsigned)(kk >> 32));
            unsigned idx = ~(unsigned)(kk & 0xFFFFFFFFu);
            int y = (int)(idx / W), x = (int)(idx % W);
            float* gtb = g_gt + (size_t)b * HW;
            #pragma unroll
            for (int dy = -2; dy <= 2; dy++) {
                int yy = y + dy; if (yy < 0 || yy >= H) continue;
                #pragma unroll
                for (int dx = -2; dx <= 2; dx++) {
                    int xx = x + dx; if (xx < 0 || xx >= W) continue;
                    atomicAdd(&gtb[yy*W + xx], v * g_gauss[(dy+2)*5 + (dx+2)]);
                }
            }
        }
    }
}

// -------- sparse loss correction: sum over touched pixels of gt^2 - 2*s1m*gt
// atomicExch gives exactly-once accounting AND restores g_gt to all-zero.
__global__ void corr_kernel() {
    int b = blockIdx.x;
    int n = g_selcnt[b];
    int tid = threadIdx.x;
    double acc = 0.0;
    for (int t = tid; t < n * 25; t += 256) {
        int kp = t / 25, tap = t % 25;
        unsigned long long kk = g_sel[(size_t)b*TOPK + kp];
        unsigned idx = ~(unsigned)(kk & 0xFFFFFFFFu);
        int y = (int)(idx / W) + tap / 5 - 2;
        int x = (int)(idx % W) + tap % 5 - 2;
        if (x >= 0 && x < W && y >= 0 && y < H) {
            float old = atomicExch(&g_gt[(size_t)b*HW + y*W + x], 0.f);
            if (old != 0.f) {
                float s1 = g_s1m[(size_t)b*HW + y*W + x];
                acc += (double)old * ((double)old - 2.0 * (double)s1);
            }
        }
    }
    #pragma unroll
    for (int o = 16; o > 0; o >>= 1) acc += __shfl_down_sync(0xffffffffu, acc, o);
    __shared__ double ws[8];
    if ((tid & 31) == 0) ws[tid >> 5] = acc;
    __syncthreads();
    if (tid == 0) {
        double a = 0.0;
        #pragma unroll
        for (int w = 0; w < 8; w++) a += ws[w];
        atomicAdd(&g_lossC, a);
    }
}

__global__ void final_kernel(float* __restrict__ out) {
    if (threadIdx.x == 0) {
        double S = g_lossC;
        long long nn = 0;
        #pragma unroll
        for (int b = 0; b < B; b++) { S += g_lossA[b]; nn += g_norm32[b]; }
        out[0] = (float)(S / (double)nn);
    }
}

// ------------------------------------------------------------------- launch
extern "C" void kernel_launch(void* const* d_in, const int* in_sizes, int n_in,
                              void* d_out, int out_size) {
    int hi = 2;
    if (in_sizes[0] == B*9) hi = 0;
    else if (in_sizes[1] == B*9) hi = 1;
    int s1i = (hi == 0) ? 1 : 0;
    int s2i = 3 - hi - s1i;

    const float* score1 = (const float*)d_in[s1i];
    const float* score2 = (const float*)d_in[s2i];
    const float* homo   = (const float*)d_in[hi];
    float* out = (float*)d_out;
    float* out_vis = out + 1 + (size_t)B * TOPK * 2;

    static bool attr_done = false;
    if (!attr_done) {
        cudaFuncSetAttribute(select_kernel,
                             cudaFuncAttributeMaxDynamicSharedMemorySize,
                             MAXC * (int)sizeof(unsigned long long));
        attr_done = true;
    }

    dim3 blk(32, 8);
    init_kernel<<<1, 256>>>();
    mega_kernel<<<dim3(W/32, H/8, B), blk>>>(score1, score2, homo, out_vis);
    select_kernel<<<dim3(B, 2), 1024, MAXC * sizeof(unsigned long long)>>>(out);
    corr_kernel<<<B, 256>>>();
    final_kernel<<<1, 32>>>(out);
}

// round 4
// speedup vs baseline: 1.4828x; 1.4828x over previous
#include <cuda_runtime.h>
#include <math.h>
#include <stdint.h>

#define B 32
#define H 480
#define W 640
#define HW (H*W)
#define NPIX (B*HW)
#define TOPK 1024
#define MAXC 16384
#define CORR_SPLIT 8

// ---- scratch (device globals; zero-initialized at load, self-restoring) ----
__device__ float g_gt[NPIX];                       // sparse gt map (zero invariant across replays)
__device__ unsigned long long g_cand[2ULL*B*MAXC]; // candidate keys, 2 streams
__device__ unsigned long long g_sel[B*TOPK];       // selected gt keys (for correction)
__device__ int    g_cnt[2*B];
__device__ int    g_selcnt[B];
__device__ int    g_norm32[B];
__device__ double g_lossA[B];                      // sum s1m^2 per batch
__device__ double g_lossC;                         // sparse correction
__device__ float  g_gauss[25];

// ---------------------------------------------------------------- init
__global__ void init_kernel() {
    int i = threadIdx.x;
    if (i < 2*B) g_cnt[i] = 0;
    if (i < B)   { g_selcnt[i] = 0; g_norm32[i] = 0; g_lossA[i] = 0.0; }
    if (i == 0)  g_lossC = 0.0;
    if (i < 25) {
        int r = i / 5, c = i % 5;
        double g[5]; double s = 0.0;
        #pragma unroll
        for (int t = 0; t < 5; t++) { g[t] = exp(-((double)((t-2)*(t-2))) / 8.0); s += g[t]; }
        g_gauss[i] = (float)(g[r] * g[c] / (s * s));
    }
}

// warp-aggregated candidate append (all 32 lanes must reach this call)
__device__ __forceinline__ void append_cand(int list, bool is_cand, unsigned long long key,
                                            int lane) {
    unsigned m = __ballot_sync(0xffffffffu, is_cand);
    if (m) {
        int leader = __ffs(m) - 1;
        int base = 0;
        if (lane == leader) base = atomicAdd(&g_cnt[list], __popc(m));
        base = __shfl_sync(0xffffffffu, base, leader);
        if (is_cand) {
            int p = base + __popc(m & ((1u << lane) - 1));
            if (p < MAXC) g_cand[(size_t)list * MAXC + p] = key;
        }
    }
}

// --------- fused warp + erode + mask + bilinear + NMS + partial-loss pass ---
// tile: 64x16 pixels per 256-thread block; each thread owns 4 pixels (2x2 quads)
// mask region:  gy in [by-3, by+18] (22 rows), gx in [bx-3, bx+66] (70 cols)
// value region: gy in [by-2, by+17] (20 rows), gx in [bx-2, bx+65] (68 cols)
__global__ void __launch_bounds__(256) mega_kernel(
        const float* __restrict__ score1,
        const float* __restrict__ score2,
        const float* __restrict__ homo,
        float* __restrict__ out_vis) {
    __shared__ float h[9];
    __shared__ float spx[22][72];
    __shared__ float spy[22][72];
    __shared__ unsigned char mk[22][72];
    __shared__ unsigned char se[20][72];
    __shared__ float t1[20][72];
    __shared__ float t2[20][72];
    __shared__ float hm1[20][64];
    __shared__ float hm2[20][64];
    __shared__ double red_d[8];
    __shared__ int    red_i[8];

    int b  = blockIdx.z;
    int bx = blockIdx.x * 64, by = blockIdx.y * 16;
    int tx = threadIdx.x, ty = threadIdx.y;
    int tid = ty * 32 + tx, lane = tx;
    if (tid < 9) h[tid] = homo[b*9 + tid];
    __syncthreads();

    // Pass A: warped coords + visibility for the mask region
    for (int j = tid; j < 22*70; j += 256) {
        int r = j / 70, c = j % 70;
        float X = (float)(bx - 3 + c), Y = (float)(by - 3 + r);
        bool inimg = (bx-3+c) >= 0 && (bx-3+c) < W && (by-3+r) >= 0 && (by-3+r) < H;
        float z  = __fmaf_rn(h[6], X, __fmaf_rn(h[7], Y, h[8])) + 1e-8f;
        float px = __fmaf_rn(h[0], X, __fmaf_rn(h[1], Y, h[2])) / z;
        float py = __fmaf_rn(h[3], X, __fmaf_rn(h[4], Y, h[5])) / z;
        spx[r][c] = px; spy[r][c] = py;
        // bilinear(ones) > 0  <=>  px in (-1, W) and py in (-1, H)
        bool vis = inimg && (px > -1.f) && (px < (float)W) && (py > -1.f) && (py < (float)H);
        mk[r][c] = vis ? 1 : 0;
    }
    __syncthreads();

    // Pass B: eroded mask + masked values (s1, warped s2) for the value region
    const float* img1 = score1 + (size_t)b * HW;
    const float* img2 = score2 + (size_t)b * HW;
    for (int j = tid; j < 20*68; j += 256) {
        int r = j / 68, c = j % 68;
        int gy = by - 2 + r, gx = bx - 2 + c;
        float v1 = -INFINITY, v2 = -INFINITY;
        int e = 0;
        if (gx >= 0 && gx < W && gy >= 0 && gy < H) {
            // mask index of (gy,gx) is (r+1, c+1)
            e = mk[r][c]   & mk[r][c+1]   & mk[r][c+2]
              & mk[r+1][c] & mk[r+1][c+1] & mk[r+1][c+2]
              & mk[r+2][c] & mk[r+2][c+1] & mk[r+2][c+2];
            if (e) {
                v1 = img1[gy*W + gx];
                // bilinear sample using precomputed (px,py); zero-pad outside
                float px = spx[r+1][c+1], py = spy[r+1][c+1];
                float x0 = floorf(px), y0 = floorf(py);
                float fx = px - x0, fy = py - y0;
                float v00 = 0.f, v01 = 0.f, v10 = 0.f, v11 = 0.f;
                if (x0     >= 0.f && x0     <= (float)(W-1) && y0     >= 0.f && y0     <= (float)(H-1)) v00 = img2[(int)y0 * W + (int)x0];
                if (x0+1.f >= 0.f && x0+1.f <= (float)(W-1) && y0     >= 0.f && y0     <= (float)(H-1)) v01 = img2[(int)y0 * W + (int)(x0+1.f)];
                if (x0     >= 0.f && x0     <= (float)(W-1) && y0+1.f >= 0.f && y0+1.f <= (float)(H-1)) v10 = img2[(int)(y0+1.f) * W + (int)x0];
                if (x0+1.f >= 0.f && x0+1.f <= (float)(W-1) && y0+1.f >= 0.f && y0+1.f <= (float)(H-1)) v11 = img2[(int)(y0+1.f) * W + (int)(x0+1.f)];
                v2 = v00*(1.f-fx)*(1.f-fy) + v01*fx*(1.f-fy) + v10*(1.f-fx)*fy + v11*fx*fy;
            } else {
                v1 = 0.f; v2 = 0.f;   // in-image but masked out
            }
        }
        se[r][c] = (unsigned char)e;
        t1[r][c] = v1; t2[r][c] = v2;
    }
    __syncthreads();

    // Pass C: horizontal 5-max
    for (int j = tid; j < 20*64; j += 256) {
        int r = j / 64, c = j % 64;
        float m1 = t1[r][c], m2 = t2[r][c];
        #pragma unroll
        for (int d = 1; d < 5; d++) {
            m1 = fmaxf(m1, t1[r][c+d]);
            m2 = fmaxf(m2, t2[r][c+d]);
        }
        hm1[r][c] = m1; hm2[r][c] = m2;
    }
    __syncthreads();

    // Pass D: per-pixel NMS + outputs + partial loss/norm
    double acc = 0.0;
    int cnt = 0;
    #pragma unroll
    for (int q = 0; q < 4; q++) {
        int lx = tx + (q & 1) * 32;
        int ly = ty + (q >> 1) * 8;
        float s1v = t1[ly+2][lx+2];
        float w2v = t2[ly+2][lx+2];
        int e = se[ly+2][lx+2];
        float vm1 = hm1[ly][lx], vm2 = hm2[ly][lx];
        #pragma unroll
        for (int d = 1; d < 5; d++) {
            vm1 = fmaxf(vm1, hm1[ly+d][lx]);
            vm2 = fmaxf(vm2, hm2[ly+d][lx]);
        }
        int x = bx + lx, y = by + ly;
        size_t i = (size_t)b * HW + (size_t)y * W + x;
        out_vis[i] = e ? 1.f : 0.f;

        int idx = y*W + x;
        unsigned long long key1 = ((unsigned long long)__float_as_uint(s1v) << 32) | (unsigned)(~idx);
        unsigned long long key2 = ((unsigned long long)__float_as_uint(w2v) << 32) | (unsigned)(~idx);
        append_cand(b,     (s1v > 0.3f) && (s1v == vm1), key1, lane);
        append_cand(B + b, (w2v > 0.3f) && (w2v == vm2), key2, lane);

        acc += (double)s1v * (double)s1v;
        cnt += e;
    }

    // block reduction -> one atomic per block
    #pragma unroll
    for (int o = 16; o > 0; o >>= 1) {
        acc += __shfl_down_sync(0xffffffffu, acc, o);
        cnt += __shfl_down_sync(0xffffffffu, cnt, o);
    }
    int wid = tid >> 5;
    if (lane == 0) { red_d[wid] = acc; red_i[wid] = cnt; }
    __syncthreads();
    if (tid == 0) {
        double a = 0.0; int c = 0;
        #pragma unroll
        for (int w = 0; w < 8; w++) { a += red_d[w]; c += red_i[w]; }
        atomicAdd(&g_lossA[b], a);
        atomicAdd(&g_norm32[b], c);
    }
}

// ------------------------------------ top-1024 select + sort + kp/gt output
__global__ void __launch_bounds__(1024) select_kernel(float* __restrict__ out) {
    extern __shared__ unsigned long long sk[];      // cached candidate keys (MAXC)
    __shared__ unsigned long long sel[TOPK];
    __shared__ unsigned int hist[256];
    __shared__ unsigned long long sh_pref;
    __shared__ unsigned int sh_rem;
    __shared__ int sh_cnt;

    int b = blockIdx.x, s = blockIdx.y;
    int li = s*B + b;
    int n = g_cnt[li]; if (n > MAXC) n = MAXC;
    const unsigned long long* keys = g_cand + (size_t)li * MAXC;
    int tid = threadIdx.x;

    sel[tid] = 0ULL;
    if (tid == 0) { sh_pref = 0ULL; sh_rem = TOPK; sh_cnt = 0; }
    for (int i = tid; i < n; i += 1024) sk[i] = keys[i];
    __syncthreads();

    if (n > TOPK) {
        // radix-select the exact 1024th-largest key (keys unique via idx bits)
        for (int shift = 56; shift >= 0; shift -= 8) {
            if (tid < 256) hist[tid] = 0;
            __syncthreads();
            unsigned long long pref  = sh_pref;
            unsigned long long pmask = (shift == 56) ? 0ULL : (~0ULL << (shift + 8));
            for (int i = tid; i < n; i += 1024) {
                unsigned long long k = sk[i];
                if ((k & pmask) == pref)
                    atomicAdd(&hist[(unsigned)(k >> shift) & 255u], 1u);
            }
            __syncthreads();
            if (tid == 0) {
                unsigned rem = sh_rem;
                for (int bin = 255; bin >= 0; bin--) {
                    unsigned c = hist[bin];
                    if (c < rem) rem -= c;
                    else { sh_pref = pref | ((unsigned long long)bin << shift); break; }
                }
                sh_rem = rem;
            }
            __syncthreads();
        }
        unsigned long long kth = sh_pref;
        for (int i = tid; i < n; i += 1024) {
            unsigned long long k = sk[i];
            if (k >= kth) { int p = atomicAdd(&sh_cnt, 1); if (p < TOPK) sel[p] = k; }
        }
    } else {
        if (tid < n) sel[tid] = sk[tid];
    }
    __syncthreads();

    int m = (n < TOPK) ? n : TOPK;

    if (s == 0) {
        // sort needed only for kp output order: bitonic, descending
        for (unsigned k = 2; k <= TOPK; k <<= 1) {
            for (unsigned j = k >> 1; j > 0; j >>= 1) {
                unsigned i = (unsigned)tid, ixj = i ^ j;
                if (ixj > i) {
                    unsigned long long a = sel[i], c = sel[ixj];
                    bool up = ((i & k) == 0);
                    bool sw = up ? (a < c) : (a > c);
                    if (sw) { sel[i] = c; sel[ixj] = a; }
                }
                __syncthreads();
            }
        }
        if (tid < m) {
            unsigned idx = ~(unsigned)(sel[tid] & 0xFFFFFFFFu);
            out[1 + ((size_t)b*TOPK + tid)*2]     = (float)(idx / W);
            out[1 + ((size_t)b*TOPK + tid)*2 + 1] = (float)(idx % W);
        }
        __syncthreads();
        // jax top_k pad semantics: remaining slots = lowest zero-valued indices
        if (tid == 0 && m < TOPK) {
            int cursor = 0;
            for (int j = m; j < TOPK; j++) {
                for (;;) {
                    bool isc = false;
                    for (int t = 0; t < m; t++) {
                        unsigned idx = ~(unsigned)(sel[t] & 0xFFFFFFFFu);
                        if ((int)idx == cursor) { isc = true; break; }
                    }
                    if (!isc) break;
                    cursor++;
                }
                out[1 + ((size_t)b*TOPK + j)*2]     = (float)(cursor / W);
                out[1 + ((size_t)b*TOPK + j)*2 + 1] = (float)(cursor % W);
                cursor++;
            }
        }
    } else {
        // gt stream: no sort needed; persist selection + scatter gaussians
        if (tid == 0) g_selcnt[b] = m;
        if (tid < m) {
            unsigned long long kk = sel[tid];
            g_sel[(size_t)b*TOPK + tid] = kk;
            float v = __uint_as_float((unsigned)(kk >> 32));
            unsigned idx = ~(unsigned)(kk & 0xFFFFFFFFu);
            int y = (int)(idx / W), x = (int)(idx % W);
            float* gtb = g_gt + (size_t)b * HW;
            #pragma unroll
            for (int dy = -2; dy <= 2; dy++) {
                int yy = y + dy; if (yy < 0 || yy >= H) continue;
                #pragma unroll
                for (int dx = -2; dx <= 2; dx++) {
                    int xx = x + dx; if (xx < 0 || xx >= W) continue;
                    atomicAdd(&gtb[yy*W + xx], v * g_gauss[(dy+2)*5 + (dx+2)]);
                }
            }
        }
    }
}

// -------- sparse loss correction: sum over touched pixels of gt^2 - 2*s1m*gt
// atomicExch gives exactly-once accounting AND restores g_gt to all-zero.
__global__ void corr_kernel(const float* __restrict__ score1,
                            const float* __restrict__ vis) {
    int b = blockIdx.x;
    int n = g_selcnt[b];
    int tid = blockIdx.y * blockDim.x + threadIdx.x;
    double acc = 0.0;
    for (int t = tid; t < n * 25; t += CORR_SPLIT * 256) {
        int kp = t / 25, tap = t % 25;
        unsigned long long kk = g_sel[(size_t)b*TOPK + kp];
        unsigned idx = ~(unsigned)(kk & 0xFFFFFFFFu);
        int y = (int)(idx / W) + tap / 5 - 2;
        int x = (int)(idx % W) + tap % 5 - 2;
        if (x >= 0 && x < W && y >= 0 && y < H) {
            size_t i = (size_t)b*HW + y*W + x;
            float old = atomicExch(&g_gt[i], 0.f);
            if (old != 0.f) {
                float s1 = score1[i] * vis[i];
                acc += (double)old * ((double)old - 2.0 * (double)s1);
            }
        }
    }
    #pragma unroll
    for (int o = 16; o > 0; o >>= 1) acc += __shfl_down_sync(0xffffffffu, acc, o);
    __shared__ double ws[8];
    int lt = threadIdx.x;
    if ((lt & 31) == 0) ws[lt >> 5] = acc;
    __syncthreads();
    if (lt == 0) {
        double a = 0.0;
        #pragma unroll
        for (int w = 0; w < 8; w++) a += ws[w];
        atomicAdd(&g_lossC, a);
    }
}

__global__ void final_kernel(float* __restrict__ out) {
    if (threadIdx.x == 0) {
        double S = g_lossC;
        long long nn = 0;
        #pragma unroll
        for (int b = 0; b < B; b++) { S += g_lossA[b]; nn += g_norm32[b]; }
        out[0] = (float)(S / (double)nn);
    }
}

// ------------------------------------------------------------------- launch
extern "C" void kernel_launch(void* const* d_in, const int* in_sizes, int n_in,
                              void* d_out, int out_size) {
    int hi = 2;
    if (in_sizes[0] == B*9) hi = 0;
    else if (in_sizes[1] == B*9) hi = 1;
    int s1i = (hi == 0) ? 1 : 0;
    int s2i = 3 - hi - s1i;

    const float* score1 = (const float*)d_in[s1i];
    const float* score2 = (const float*)d_in[s2i];
    const float* homo   = (const float*)d_in[hi];
    float* out = (float*)d_out;
    float* out_vis = out + 1 + (size_t)B * TOPK * 2;

    static bool attr_done = false;
    if (!attr_done) {
        cudaFuncSetAttribute(select_kernel,
                             cudaFuncAttributeMaxDynamicSharedMemorySize,
                             MAXC * (int)sizeof(unsigned long long));
        attr_done = true;
    }

    init_kernel<<<1, 256>>>();
    mega_kernel<<<dim3(W/64, H/16, B), dim3(32, 8)>>>(score1, score2, homo, out_vis);
    select_kernel<<<dim3(B, 2), 1024, MAXC * sizeof(unsigned long long)>>>(out);
    corr_kernel<<<dim3(B, CORR_SPLIT), 256>>>(score1, out_vis);
    final_kernel<<<1, 32>>>(out);
}

// round 6
// speedup vs baseline: 1.5985x; 1.0780x over previous
#include <cuda_runtime.h>
#include <math.h>
#include <stdint.h>

#define B 32
#define H 480
#define W 640
#define HW (H*W)
#define NPIX (B*HW)
#define TOPK 1024
#define MAXC 16384
#define CORR_SPLIT 32

typedef unsigned long long ull;

// ---- scratch (device globals; zero-initialized at load, self-restoring) ----
__device__ float g_gt[NPIX];                       // sparse gt map (zero invariant across replays)
__device__ ull    g_cand[2ULL*B*MAXC];             // candidate keys, 2 streams
__device__ ull    g_sel[B*TOPK];                   // selected gt keys (for correction)
__device__ int    g_cnt[2*B];
__device__ int    g_selcnt[B];
__device__ int    g_norm32[B];
__device__ double g_lossA[B];                      // sum s1m^2 per batch
__device__ double g_lossC;                         // sparse correction
__device__ float  g_gauss[25];

// ---------------------------------------------------------------- init
__global__ void init_kernel() {
    int i = threadIdx.x;
    if (i < 2*B) g_cnt[i] = 0;
    if (i < B)   { g_selcnt[i] = 0; g_norm32[i] = 0; g_lossA[i] = 0.0; }
    if (i == 0)  g_lossC = 0.0;
    if (i < 25) {
        int r = i / 5, c = i % 5;
        double g[5]; double s = 0.0;
        #pragma unroll
        for (int t = 0; t < 5; t++) { g[t] = exp(-((double)((t-2)*(t-2))) / 8.0); s += g[t]; }
        g_gauss[i] = (float)(g[r] * g[c] / (s * s));
    }
}

// warp-aggregated candidate append (all 32 lanes must reach this call)
__device__ __forceinline__ void append_cand(int list, bool is_cand, ull key, int lane) {
    unsigned m = __ballot_sync(0xffffffffu, is_cand);
    if (m) {
        int leader = __ffs(m) - 1;
        int base = 0;
        if (lane == leader) base = atomicAdd(&g_cnt[list], __popc(m));
        base = __shfl_sync(0xffffffffu, base, leader);
        if (is_cand) {
            int p = base + __popc(m & ((1u << lane) - 1));
            if (p < MAXC) g_cand[(size_t)list * MAXC + p] = key;
        }
    }
}

// --------- fused warp + erode + mask + bilinear + NMS + partial-loss pass ---
// tile 64x16 px / 256 threads. mask region 22 rows x 70 cols (gx in [bx-3,bx+66],
// gy in [by-3,by+18]); value region 20 x 68 (halo 2). Bitmask erosion.
__global__ void __launch_bounds__(256) mega_kernel(
        const float* __restrict__ score1,
        const float* __restrict__ score2,
        const float* __restrict__ homo,
        float* __restrict__ out_vis) {
    __shared__ float h[9];
    __shared__ float spx[22][70];
    __shared__ float spy[22][70];
    __shared__ unsigned mw[22][3];     // vis bitmask words
    __shared__ unsigned ew[22][3];     // horizontally eroded
    __shared__ unsigned seb[20][3];    // fully eroded, indexed by value row
    __shared__ float t1[20][72];
    __shared__ float t2[20][72];
    __shared__ float hm1[20][64];
    __shared__ float hm2[20][64];
    __shared__ float red_f[8];

    int b  = blockIdx.z;
    int bx = blockIdx.x * 64, by = blockIdx.y * 16;
    int tid = threadIdx.x;
    int lane = tid & 31, wid = tid >> 5;
    if (tid < 9) h[tid] = homo[b*9 + tid];
    __syncthreads();

    // Pass A: warped coords + vis bits (ballot per 32-col word)
    for (int task = wid; task < 66; task += 8) {
        int mr = task / 3, wj = task % 3;
        int mc = wj * 32 + lane;
        int gx = bx - 3 + mc, gy = by - 3 + mr;
        bool vis = false;
        if (mc < 70 && gx >= 0 && gx < W && gy >= 0 && gy < H) {
            float X = (float)gx, Y = (float)gy;
            float z  = __fmaf_rn(h[6], X, __fmaf_rn(h[7], Y, h[8])) + 1e-8f;
            float px = __fmaf_rn(h[0], X, __fmaf_rn(h[1], Y, h[2])) / z;
            float py = __fmaf_rn(h[3], X, __fmaf_rn(h[4], Y, h[5])) / z;
            spx[mr][mc] = px; spy[mr][mc] = py;
            // bilinear(ones) > 0  <=>  px in (-1, W) and py in (-1, H)
            vis = (px > -1.f) && (px < (float)W) && (py > -1.f) && (py < (float)H);
        }
        unsigned wmask = __ballot_sync(0xffffffffu, vis);
        if (lane == 0) mw[mr][wj] = wmask;
    }
    __syncthreads();

    // horizontal 3-erode (funnel shifts across word boundaries)
    if (tid < 66) {
        int mr = tid / 3, wj = tid % 3;
        unsigned cur = mw[mr][wj];
        unsigned nxt = (wj < 2) ? mw[mr][wj+1] : 0u;
        unsigned prv = (wj > 0) ? mw[mr][wj-1] : 0u;
        unsigned rsh = __funnelshift_r(cur, nxt, 1);       // bit c -> m[c+1]
        unsigned lsh = (cur << 1) | (prv >> 31);           // bit c -> m[c-1]
        ew[mr][wj] = cur & rsh & lsh;
    }
    __syncthreads();
    // vertical 3-erode; seb[vr] = eroded mask for value row vr (mask row vr+1)
    if (tid < 60) {
        int vr = tid / 3, wj = tid % 3;
        seb[vr][wj] = ew[vr][wj] & ew[vr+1][wj] & ew[vr+2][wj];
    }
    __syncthreads();

    // Pass B: masked values (s1, warped s2) over value region 20x68
    const float* img1 = score1 + (size_t)b * HW;
    const float* img2 = score2 + (size_t)b * HW;
    for (int j = tid; j < 20*68; j += 256) {
        int r = j / 68, c = j % 68;
        float v1 = 0.f, v2 = 0.f;
        int bi = c + 1;
        unsigned e = (seb[r][bi >> 5] >> (bi & 31)) & 1u;
        if (e) {                      // e=1 implies pixel in-image
            int gy = by - 2 + r, gx = bx - 2 + c;
            v1 = img1[gy*W + gx];
            float px = spx[r+1][c+1], py = spy[r+1][c+1];
            float x0 = floorf(px), y0 = floorf(py);
            float fx = px - x0, fy = py - y0;
            float v00 = 0.f, v01 = 0.f, v10 = 0.f, v11 = 0.f;
            if (x0     >= 0.f && x0     <= (float)(W-1) && y0     >= 0.f && y0     <= (float)(H-1)) v00 = img2[(int)y0 * W + (int)x0];
            if (x0+1.f >= 0.f && x0+1.f <= (float)(W-1) && y0     >= 0.f && y0     <= (float)(H-1)) v01 = img2[(int)y0 * W + (int)(x0+1.f)];
            if (x0     >= 0.f && x0     <= (float)(W-1) && y0+1.f >= 0.f && y0+1.f <= (float)(H-1)) v10 = img2[(int)(y0+1.f) * W + (int)x0];
            if (x0+1.f >= 0.f && x0+1.f <= (float)(W-1) && y0+1.f >= 0.f && y0+1.f <= (float)(H-1)) v11 = img2[(int)(y0+1.f) * W + (int)(x0+1.f)];
            v2 = v00*(1.f-fx)*(1.f-fy) + v01*fx*(1.f-fy) + v10*(1.f-fx)*fy + v11*fx*fy;
        }
        t1[r][c] = v1; t2[r][c] = v2;
    }
    __syncthreads();

    // Pass C: horizontal 5-max
    for (int j = tid; j < 20*64; j += 256) {
        int r = j / 64, c = j & 63;
        float m1 = t1[r][c], m2 = t2[r][c];
        #pragma unroll
        for (int d = 1; d < 5; d++) {
            m1 = fmaxf(m1, t1[r][c+d]);
            m2 = fmaxf(m2, t2[r][c+d]);
        }
        hm1[r][c] = m1; hm2[r][c] = m2;
    }
    __syncthreads();

    // Pass D: NMS + candidate appends + fp32 loss partial
    float acc = 0.f;
    #pragma unroll
    for (int q = 0; q < 4; q++) {
        int j = tid + q * 256;
        int lx = j & 63, ly = j >> 6;
        float s1v = t1[ly+2][lx+2];
        float w2v = t2[ly+2][lx+2];
        float vm1 = hm1[ly][lx], vm2 = hm2[ly][lx];
        #pragma unroll
        for (int d = 1; d < 5; d++) {
            vm1 = fmaxf(vm1, hm1[ly+d][lx]);
            vm2 = fmaxf(vm2, hm2[ly+d][lx]);
        }
        int idx = (by+ly)*W + (bx+lx);
        ull key1 = ((ull)__float_as_uint(s1v) << 32) | (unsigned)(~idx);
        ull key2 = ((ull)__float_as_uint(w2v) << 32) | (unsigned)(~idx);
        append_cand(b,     (s1v > 0.3f) && (s1v == vm1), key1, lane);
        append_cand(B + b, (w2v > 0.3f) && (w2v == vm2), key2, lane);
        acc = __fmaf_rn(s1v, s1v, acc);
    }

    // vis output: 4 scalar stores per thread (out_vis base is only 4B-aligned!)
    {
        int ry = tid >> 4;            // 0..15
        int g4 = (tid & 15) * 4;      // first x of the quad
        int vr = ry + 2;
        float* dst = out_vis + (size_t)b*HW + (size_t)(by+ry)*W + bx + g4;
        int b0 = g4 + 3;              // bit index of pixel lx = lx+3
        dst[0] = (float)((seb[vr][(b0  ) >> 5] >> ((b0  ) & 31)) & 1u);
        dst[1] = (float)((seb[vr][(b0+1) >> 5] >> ((b0+1) & 31)) & 1u);
        dst[2] = (float)((seb[vr][(b0+2) >> 5] >> ((b0+2) & 31)) & 1u);
        dst[3] = (float)((seb[vr][(b0+3) >> 5] >> ((b0+3) & 31)) & 1u);
    }

    // norm via popcount of eroded bits (output region: bits lx+3, lx in [0,64))
    if (tid < 16) {
        int vr = tid + 2;
        int cnt = __popc(seb[vr][0] >> 3) + __popc(seb[vr][1]) + __popc(seb[vr][2] & 7u);
        cnt = __reduce_add_sync(0xffffu, cnt);
        if (tid == 0) atomicAdd(&g_norm32[b], cnt);
    }

    // block loss reduction -> one double atomic
    #pragma unroll
    for (int o = 16; o > 0; o >>= 1) acc += __shfl_down_sync(0xffffffffu, acc, o);
    if (lane == 0) red_f[wid] = acc;
    __syncthreads();
    if (tid == 0) {
        float a = 0.f;
        #pragma unroll
        for (int w = 0; w < 8; w++) a += red_f[w];
        atomicAdd(&g_lossA[b], (double)a);
    }
}

// ------------------------------------ top-1024 select + sort + kp/gt output
__global__ void __launch_bounds__(1024) select_kernel(float* __restrict__ out) {
    extern __shared__ ull sk[];                     // cached candidate keys (MAXC)
    __shared__ ull sel[TOPK];
    __shared__ unsigned hist[256];
    __shared__ unsigned ssum[256];
    __shared__ ull sh_pref;
    __shared__ unsigned sh_rem;
    __shared__ int sh_cnt;
    __shared__ int sh_done;

    int b = blockIdx.x, s = blockIdx.y;
    int li = s*B + b;
    int n = g_cnt[li]; if (n > MAXC) n = MAXC;
    const ull* keys = g_cand + (size_t)li * MAXC;
    int tid = threadIdx.x;

    sel[tid] = 0ULL;
    if (tid == 0) { sh_pref = 0ULL; sh_rem = TOPK; sh_cnt = 0; sh_done = 0; }
    for (int i = tid; i < n; i += 1024) sk[i] = keys[i];
    __syncthreads();

    if (n > TOPK) {
        for (int shift = 56; shift >= 0; shift -= 8) {
            if (tid < 256) hist[tid] = 0;
            __syncthreads();
            ull pref  = sh_pref;
            ull pmask = (shift == 56) ? 0ULL : (~0ULL << (shift + 8));
            for (int i = tid; i < n; i += 1024) {
                ull k = sk[i];
                if ((k & pmask) == pref)
                    atomicAdd(&hist[(unsigned)(k >> shift) & 255u], 1u);
            }
            __syncthreads();
            // suffix sums: ssum[t] = sum_{j>=t} hist[j]
            if (tid < 256) ssum[tid] = hist[tid];
            __syncthreads();
            #pragma unroll
            for (int off = 1; off < 256; off <<= 1) {
                unsigned v = 0;
                if (tid < 256) v = ssum[tid] + ((tid + off < 256) ? ssum[tid + off] : 0u);
                __syncthreads();
                if (tid < 256) ssum[tid] = v;
                __syncthreads();
            }
            if (tid < 256) {
                unsigned rem = sh_rem;
                unsigned above = (tid < 255) ? ssum[tid+1] : 0u;
                if (ssum[tid] >= rem && above < rem) {
                    sh_pref = pref | ((ull)tid << shift);
                    sh_rem  = rem - above;
                    // exact boundary: whole bin selected -> low bits irrelevant
                    sh_done = ((ssum[tid] - above) == (rem - above)) ? 1 : 0;
                }
            }
            __syncthreads();
            if (sh_done) break;
        }
        ull kth = sh_pref;
        for (int i = tid; i < n; i += 1024) {
            ull k = sk[i];
            if (k >= kth) { int p = atomicAdd(&sh_cnt, 1); if (p < TOPK) sel[p] = k; }
        }
    } else {
        if (tid < n) sel[tid] = sk[tid];
    }
    __syncthreads();

    int m = (n < TOPK) ? n : TOPK;

    if (s == 0) {
        // bitonic sort, descending (padding zeros sink)
        for (unsigned k = 2; k <= TOPK; k <<= 1) {
            for (unsigned j = k >> 1; j > 0; j >>= 1) {
                unsigned i = (unsigned)tid, ixj = i ^ j;
                if (ixj > i) {
                    ull a = sel[i], c = sel[ixj];
                    bool up = ((i & k) == 0);
                    if (up ? (a < c) : (a > c)) { sel[i] = c; sel[ixj] = a; }
                }
                __syncthreads();
            }
        }
        if (tid < m) {
            unsigned idx = ~(unsigned)(sel[tid] & 0xFFFFFFFFu);
            out[1 + ((size_t)b*TOPK + tid)*2]     = (float)(idx / W);
            out[1 + ((size_t)b*TOPK + tid)*2 + 1] = (float)(idx % W);
        }
        __syncthreads();
        if (tid == 0 && m < TOPK) {
            int cursor = 0;
            for (int j = m; j < TOPK; j++) {
                for (;;) {
                    bool isc = false;
                    for (int t = 0; t < m; t++) {
                        unsigned idx = ~(unsigned)(sel[t] & 0xFFFFFFFFu);
                        if ((int)idx == cursor) { isc = true; break; }
                    }
                    if (!isc) break;
                    cursor++;
                }
                out[1 + ((size_t)b*TOPK + j)*2]     = (float)(cursor / W);
                out[1 + ((size_t)b*TOPK + j)*2 + 1] = (float)(cursor % W);
                cursor++;
            }
        }
    } else {
        if (tid == 0) g_selcnt[b] = m;
        if (tid < m) {
            ull kk = sel[tid];
            g_sel[(size_t)b*TOPK + tid] = kk;
            float v = __uint_as_float((unsigned)(kk >> 32));
            unsigned idx = ~(unsigned)(kk & 0xFFFFFFFFu);
            int y = (int)(idx / W), x = (int)(idx % W);
            float* gtb = g_gt + (size_t)b * HW;
            #pragma unroll
            for (int dy = -2; dy <= 2; dy++) {
                int yy = y + dy; if (yy < 0 || yy >= H) continue;
                #pragma unroll
                for (int dx = -2; dx <= 2; dx++) {
                    int xx = x + dx; if (xx < 0 || xx >= W) continue;
                    atomicAdd(&gtb[yy*W + xx], v * g_gauss[(dy+2)*5 + (dx+2)]);
                }
            }
        }
    }
}

// -------- sparse loss correction: sum over touched pixels of gt^2 - 2*s1m*gt
// atomicExch gives exactly-once accounting AND restores g_gt to all-zero.
__global__ void corr_kernel(const float* __restrict__ score1,
                            const float* __restrict__ vis) {
    int b = blockIdx.x;
    int n = g_selcnt[b];
    int tid = blockIdx.y * blockDim.x + threadIdx.x;
    double acc = 0.0;
    for (int t = tid; t < n * 25; t += CORR_SPLIT * 256) {
        int kp = t / 25, tap = t % 25;
        ull kk = g_sel[(size_t)b*TOPK + kp];
        unsigned idx = ~(unsigned)(kk & 0xFFFFFFFFu);
        int y = (int)(idx / W) + tap / 5 - 2;
        int x = (int)(idx % W) + tap % 5 - 2;
        if (x >= 0 && x < W && y >= 0 && y < H) {
            size_t i = (size_t)b*HW + y*W + x;
            float old = atomicExch(&g_gt[i], 0.f);
            if (old != 0.f) {
                float s1 = score1[i] * vis[i];
                acc += (double)old * ((double)old - 2.0 * (double)s1);
            }
        }
    }
    #pragma unroll
    for (int o = 16; o > 0; o >>= 1) acc += __shfl_down_sync(0xffffffffu, acc, o);
    __shared__ double ws[8];
    int lt = threadIdx.x;
    if ((lt & 31) == 0) ws[lt >> 5] = acc;
    __syncthreads();
    if (lt == 0) {
        double a = 0.0;
        #pragma unroll
        for (int w = 0; w < 8; w++) a += ws[w];
        atomicAdd(&g_lossC, a);
    }
}

__global__ void final_kernel(float* __restrict__ out) {
    if (threadIdx.x == 0) {
        double S = g_lossC;
        long long nn = 0;
        #pragma unroll
        for (int b = 0; b < B; b++) { S += g_lossA[b]; nn += g_norm32[b]; }
        out[0] = (float)(S / (double)nn);
    }
}

// ------------------------------------------------------------------- launch
extern "C" void kernel_launch(void* const* d_in, const int* in_sizes, int n_in,
                              void* d_out, int out_size) {
    int hi = 2;
    if (in_sizes[0] == B*9) hi = 0;
    else if (in_sizes[1] == B*9) hi = 1;
    int s1i = (hi == 0) ? 1 : 0;
    int s2i = 3 - hi - s1i;

    const float* score1 = (const float*)d_in[s1i];
    const float* score2 = (const float*)d_in[s2i];
    const float* homo   = (const float*)d_in[hi];
    float* out = (float*)d_out;
    float* out_vis = out + 1 + (size_t)B * TOPK * 2;

    static bool attr_done = false;
    if (!attr_done) {
        cudaFuncSetAttribute(select_kernel,
                             cudaFuncAttributeMaxDynamicSharedMemorySize,
                             MAXC * (int)sizeof(ull));
        attr_done = true;
    }

    init_kernel<<<1, 256>>>();
    mega_kernel<<<dim3(W/64, H/16, B), 256>>>(score1, score2, homo, out_vis);
    select_kernel<<<dim3(B, 2), 1024, MAXC * sizeof(ull)>>>(out);
    corr_kernel<<<dim3(B, CORR_SPLIT), 256>>>(score1, out_vis);
    final_kernel<<<1, 32>>>(out);
}